// round 15
// baseline (speedup 1.0000x reference)
#include <cuda_runtime.h>
#include <math.h>
#include <float.h>
#include <stdint.h>

#define TT   4096
#define HD   1024
#define EDN  8
#define NE   9
#define IDY  512
#define IFX  2048
#define CAPV 640
#define TOPK 4
#define TOPP 0.75f
#define JEPS2 0.2f

// ---- mma.sync tf32 GEMM tiling: CTA 128x128x32, 8 warps (2x4), warp 64x32 --
#define BM   128
#define BN   128
#define BK   32
#define BKP  36
#define NSTG 3
#define STAGE_FLOATS ((BM + BN) * BKP)         // 9216
#define GEMM_SMEM (NSTG * STAGE_FLOATS * 4)    // 110592 B -> 2 CTAs/SM

__device__ __forceinline__ uint32_t smem_u32(const void* p) {
    uint32_t a;
    asm("{ .reg .u64 t; cvta.to.shared.u64 t, %1; cvt.u32.u64 %0, t; }" : "=r"(a) : "l"(p));
    return a;
}
__device__ __forceinline__ void cp_async16(uint32_t dst, const void* src) {
    asm volatile("cp.async.cg.shared.global [%0], [%1], 16;" :: "r"(dst), "l"(src));
}
template<int N> __device__ __forceinline__ void cp_wait() {
    asm volatile("cp.async.wait_group %0;" :: "n"(N) : "memory");
}
__device__ __forceinline__ float rna_tf32(float x) {
    uint32_t u;
    asm("cvt.rna.tf32.f32 %0, %1;" : "=r"(u) : "f"(x));
    return __uint_as_float(u);
}
__device__ __forceinline__ void ldsm_x4(uint32_t& r0, uint32_t& r1,
                                        uint32_t& r2, uint32_t& r3, uint32_t addr) {
    asm volatile("ldmatrix.sync.aligned.m8n8.x4.shared.b16 {%0,%1,%2,%3}, [%4];"
                 : "=r"(r0), "=r"(r1), "=r"(r2), "=r"(r3) : "r"(addr));
}
__device__ __forceinline__ float silu_mul_rna(float g, float u) {
    return rna_tf32(g / (1.f + expf(-g)) * u);
}

// ----------------- device scratch (static, no allocations) -----------------
__device__ float d_logits[TT * NE];
__device__ int   d_sel[TT * TOPK];
__device__ float d_rw[TT * TOPK];
__device__ unsigned d_maskbits[TT];
__device__ int   d_kept[TT * EDN];
__device__ int   d_counts[EDN];
__device__ int   d_etok[EDN * CAPV];
__device__ int   d_tokpos[TT * TOPK];
__device__ int   d_toke[TT * TOPK];
__device__ float d_tokw[TT * TOPK];
__device__ float d_wsh[TT];
__device__ float d_xe[(size_t)EDN * CAPV * HD];
__device__ float d_hbuf[(size_t)EDN * CAPV * IDY];
__device__ float d_ybuf[(size_t)EDN * CAPV * HD];
__device__ float d_hs[(size_t)TT * IFX];
// tf32-rounded copies
__device__ float d_xr[(size_t)TT * HD];
__device__ float d_dgw_r[(size_t)EDN * IDY * HD];
__device__ float d_duw_r[(size_t)EDN * IDY * HD];
__device__ float d_ddw_r[(size_t)EDN * HD * IDY];
__device__ float d_sgw_r[(size_t)IFX * HD];
__device__ float d_suw_r[(size_t)IFX * HD];
__device__ float d_sdw_r[(size_t)HD * IFX];

// ----------------- K0: segmented round-to-tf32 prepass ----------------------
#define SEG_DW (EDN * IDY * HD / 4)
#define SEG_SW (IFX * HD / 4)
#define SEG_X  (TT * HD / 4)
#define ROUND_TOTAL (3L*SEG_DW + 3L*SEG_SW + SEG_X)
__global__ __launch_bounds__(256) void round_all_kernel(
    const float4* __restrict__ dgw, const float4* __restrict__ duw,
    const float4* __restrict__ ddw, const float4* __restrict__ sgw,
    const float4* __restrict__ suw, const float4* __restrict__ sdw,
    const float4* __restrict__ x)
{
    long i = (long)blockIdx.x * blockDim.x + threadIdx.x;
    const float4* src; float4* dst; long off;
    if (i < SEG_DW)            { src = dgw; dst = (float4*)d_dgw_r; off = i; }
    else if (i < 2L*SEG_DW)    { src = duw; dst = (float4*)d_duw_r; off = i - SEG_DW; }
    else if (i < 3L*SEG_DW)    { src = ddw; dst = (float4*)d_ddw_r; off = i - 2L*SEG_DW; }
    else if (i < 3L*SEG_DW + SEG_SW)   { src = sgw; dst = (float4*)d_sgw_r; off = i - 3L*SEG_DW; }
    else if (i < 3L*SEG_DW + 2L*SEG_SW){ src = suw; dst = (float4*)d_suw_r; off = i - 3L*SEG_DW - SEG_SW; }
    else if (i < 3L*SEG_DW + 3L*SEG_SW){ src = sdw; dst = (float4*)d_sdw_r; off = i - 3L*SEG_DW - 2L*SEG_SW; }
    else if (i < ROUND_TOTAL)  { src = x;   dst = (float4*)d_xr;    off = i - 3L*SEG_DW - 3L*SEG_SW; }
    else return;
    float4 v = src[off];
    v.x = rna_tf32(v.x); v.y = rna_tf32(v.y);
    v.z = rna_tf32(v.z); v.w = rna_tf32(v.w);
    dst[off] = v;
}

// ----------------- K1: router logits ---------------------------------------
__global__ __launch_bounds__(256) void logits_kernel(
    const float* __restrict__ x, const float* __restrict__ gw)
{
    int widx = blockIdx.x * 8 + (threadIdx.x >> 5);
    if (widx >= TT * NE) return;
    int t = widx / NE, e = widx - t * NE;
    int lane = threadIdx.x & 31;
    const float4* xr = (const float4*)(x + (size_t)t * HD);
    const float4* wr = (const float4*)(gw + (size_t)e * HD);
    float s = 0.f;
#pragma unroll
    for (int i = 0; i < HD / 128; i++) {
        float4 a = xr[lane + i * 32];
        float4 b = wr[lane + i * 32];
        s += a.x * b.x + a.y * b.y + a.z * b.z + a.w * b.w;
    }
#pragma unroll
    for (int o = 16; o; o >>= 1) s += __shfl_xor_sync(0xffffffffu, s, o);
    if (!lane) d_logits[widx] = s;
}

// ----------------- K2: per-token routing (packs mask bits) ------------------
__global__ void routing_kernel()
{
    int t = blockIdx.x * blockDim.x + threadIdx.x;
    if (t >= TT) return;

    float s[EDN];
#pragma unroll
    for (int e = 0; e < EDN; e++) s[e] = d_logits[t * NE + e];

    float m = s[0];
#pragma unroll
    for (int e = 1; e < EDN; e++) m = fmaxf(m, s[e]);
    float p[EDN]; float den = 0.f;
#pragma unroll
    for (int e = 0; e < EDN; e++) { p[e] = expf(s[e] - m); den += p[e]; }
#pragma unroll
    for (int e = 0; e < EDN; e++) p[e] /= den;
    float sp[EDN];
#pragma unroll
    for (int e = 0; e < EDN; e++) sp[e] = p[e];
    for (int i = 1; i < EDN; i++) {
        float v = sp[i]; int j = i - 1;
        while (j >= 0 && sp[j] < v) { sp[j + 1] = sp[j]; j--; }
        sp[j + 1] = v;
    }
    float c = 0.f; int cnt = 0;
#pragma unroll
    for (int e = 0; e < EDN; e++) { c += sp[e]; if (c < TOPP) cnt++; }
    int dyn_k = min(cnt + 1, TOPK);

    float masked[EDN];
#pragma unroll
    for (int e = 0; e < EDN; e++) masked[e] = s[e];
    float mult[TOPK]; int sel[TOPK];
    for (int k = 0; k < TOPK; k++) {
        float thr = masked[0]; int sl = 0;
        for (int e = 1; e < EDN; e++)
            if (masked[e] > thr) { thr = masked[e]; sl = e; }
        bool keep[EDN];
        float gm = -INFINITY;
        for (int e = 0; e < EDN; e++) {
            float fac = fmaxf(fabsf(s[e]), fabsf(thr));
            float jm = (thr - s[e]) / fac;
            keep[e] = !(jm > JEPS2);
            if (keep[e]) gm = fmaxf(gm, masked[e]);
        }
        float d2 = 0.f;
        for (int e = 0; e < EDN; e++)
            if (keep[e]) d2 += expf(masked[e] - gm);
        mult[k] = expf(thr - gm) / d2;
        sel[k] = sl;
        masked[sl] = -INFINITY;
    }
    float rsum = 0.f;
#pragma unroll
    for (int k = 0; k < TOPK; k++) {
        if (k >= dyn_k) mult[k] = 0.f;
        rsum += mult[k];
    }
    unsigned mk = 0;
#pragma unroll
    for (int k = 0; k < TOPK; k++) {
        float r = mult[k] / rsum;
        d_rw[t * TOPK + k] = r;
        d_sel[t * TOPK + k] = sel[k];
        if (mult[k] > 0.f) mk |= (1u << sel[k]);
    }
    d_maskbits[t] = mk;
}

// ----------------- K3: capacity scan (8 CTAs, 1024 thr, block scan) ---------
__global__ __launch_bounds__(1024) void scan_kernel()
{
    int e = blockIdx.x;
    int lane = threadIdx.x & 31, w = threadIdx.x >> 5;
    __shared__ int woff[32];
    __shared__ int tot_s;
    if (threadIdx.x == 0) d_counts[e] = 0;
    int carry = 0;
    __syncthreads();
    for (int c0 = 0; c0 < TT / 1024; c0++) {
        int t = c0 * 1024 + threadIdx.x;
        int v = (int)((d_maskbits[t] >> e) & 1u);
        unsigned bal = __ballot_sync(0xffffffffu, v);
        int pre = __popc(bal & ((1u << lane) - 1));
        if (lane == 0) woff[w] = __popc(bal);
        __syncthreads();
        if (w == 0) {
            int val = woff[lane];
            int ex = val;
#pragma unroll
            for (int o = 1; o < 32; o <<= 1) {
                int n = __shfl_up_sync(0xffffffffu, ex, o);
                if (lane >= o) ex += n;
            }
            woff[lane] = ex - val;
            if (lane == 31) tot_s = ex;
        }
        __syncthreads();
        int incl = carry + woff[w] + pre + v;
        d_kept[t * EDN + e] = (v && incl <= CAPV) ? 1 : 0;
        carry += tot_s;
        __syncthreads();
    }
}

// ----------------- K4: masked softmax + compaction --------------------------
__global__ void finalize_kernel()
{
    int t = blockIdx.x * blockDim.x + threadIdx.x;
    if (t >= TT) return;
    float l[NE];
#pragma unroll
    for (int i = 0; i < NE; i++) l[i] = d_logits[t * NE + i];
    int km[EDN];
#pragma unroll
    for (int e = 0; e < EDN; e++) km[e] = d_kept[t * EDN + e];

    float m = l[EDN];
#pragma unroll
    for (int e = 0; e < EDN; e++) if (km[e]) m = fmaxf(m, l[e]);
    float den = 0.f, dynsum = 0.f;
#pragma unroll
    for (int e = 0; e < EDN; e++)
        if (km[e]) { float ex = expf(l[e] - m); den += ex; dynsum += ex; }
    float exsh = expf(l[EDN] - m);
    den += exsh;
    d_wsh[t] = exsh / den;
    float sumdyn = dynsum / den;

#pragma unroll
    for (int k = 0; k < TOPK; k++) {
        float r = d_rw[t * TOPK + k];
        int e = d_sel[t * TOPK + k];
        int pos = -1;
        if (r > 0.f && km[e]) {
            pos = atomicAdd(&d_counts[e], 1);
            d_etok[e * CAPV + pos] = t;
            d_toke[t * TOPK + k] = e;
            d_tokw[t * TOPK + k] = r * sumdyn;
        }
        d_tokpos[t * TOPK + k] = pos;
    }
}

// ----------------- K5: gather x rows per expert (tf32-rounded) --------------
__global__ __launch_bounds__(256) void gather_kernel(const float* __restrict__ x)
{
    int b = blockIdx.x;
    int e = b / CAPV, i = b - e * CAPV;
    int c = threadIdx.x;
    float4* dst = (float4*)(d_xe + ((size_t)e * CAPV + i) * HD);
    if (i < d_counts[e]) {
        int t = d_etok[e * CAPV + i];
        float4 v = ((const float4*)(x + (size_t)t * HD))[c];
        v.x = rna_tf32(v.x); v.y = rna_tf32(v.y);
        v.z = rna_tf32(v.z); v.w = rna_tf32(v.w);
        dst[c] = v;
    } else {
        dst[c] = make_float4(0.f, 0.f, 0.f, 0.f);
    }
}

// ===================== fused gate+up GEMM + silu ============================
// CTA computes a 128(M) x 64(cols) h tile: B smem rows interleave gate/up at
// 8-row granularity. Fragment nf even = gate, nf odd = up for SAME cols ->
// thread-local silu. K = HD = 1024 always. Shared segment uses 8x8 CTA
// grouping (64-CTA groups share 8 A-tiles + 8 B-tiles) to cut L2 traffic 4x.
__global__ __launch_bounds__(256, 2) void gemm_gateup_fused(
    const float* __restrict__ xr, const float* __restrict__ sgw,
    const float* __restrict__ suw, float* __restrict__ hsO,
    const float* __restrict__ xe, const float* __restrict__ dgw,
    const float* __restrict__ duw, float* __restrict__ hO)
{
    extern __shared__ float smem[];
    int b = blockIdx.x;
    const float *Ap, *Bg_, *Bu_; float* Hp; int N, ty, tx;
    if (b < 1024) {                      // shared expert: 32 y x 32 x(64-col)
        N = IFX;
        int g = b >> 6, w6 = b & 63;     // 16 groups of 8x8
        int gy = w6 >> 3, gx = w6 & 7;
        ty = (g >> 2) * 8 + gy;          // 0..31
        tx = (g & 3) * 8 + gx;           // 0..31
        Ap = xr; Bg_ = sgw; Bu_ = suw; Hp = hsO;
    } else {                             // dyn: 8 experts x (5 y x 8 x)
        N = IDY;
        int idx = b - 1024;              // [0,320)
        int e = idx / 40, t = idx - e * 40;
        ty = t >> 3; tx = t & 7;
        Ap = xe + (size_t)e * CAPV * HD;
        Bg_ = dgw + (size_t)e * IDY * HD;
        Bu_ = duw + (size_t)e * IDY * HD;
        Hp = hO + (size_t)e * CAPV * IDY;
    }
    int rowBase = ty * BM, colBase = tx * 64;
    const int K = HD;

    int tid = threadIdx.x;
    int w = tid >> 5, lane = tid & 31;
    int wm = w >> 2, wn = w & 3;
    int grp = lane >> 2, tig = lane & 3;
    int q = lane >> 3, r8 = lane & 7;
    int aRow = (q & 1) * 8 + r8, aK = (q >> 1) * 4;
    int bRow = (q >> 1) * 8 + r8, bK = (q & 1) * 4;

    const float* aSrc[4];
    const float* bSrc[4];
    int sRow[4];
#pragma unroll
    for (int i = 0; i < 4; i++) {
        int idx = tid + i * 256, row = idx >> 3;
        sRow[i] = row;
        aSrc[i] = Ap + (size_t)(rowBase + row) * K;
        int t8 = row >> 4, sub = (row >> 3) & 1;
        int wRow = colBase + (t8 << 3) + (row & 7);
        bSrc[i] = (sub ? Bu_ : Bg_) + (size_t)wRow * K;
    }
    int cOfs[4];
#pragma unroll
    for (int i = 0; i < 4; i++) cOfs[i] = ((tid + i * 256) & 7) * 4;

    float acc[4][4][4] = {};
    const int KT = K / BK;

#pragma unroll
    for (int pt = 0; pt < NSTG - 1; pt++) {
        float* dstA = smem + pt * STAGE_FLOATS;
        float* dstB = dstA + BM * BKP;
#pragma unroll
        for (int i = 0; i < 4; i++)
            cp_async16(smem_u32(dstA + sRow[i] * BKP + cOfs[i]),
                       aSrc[i] + pt * BK + cOfs[i]);
#pragma unroll
        for (int i = 0; i < 4; i++)
            cp_async16(smem_u32(dstB + sRow[i] * BKP + cOfs[i]),
                       bSrc[i] + pt * BK + cOfs[i]);
        asm volatile("cp.async.commit_group;" ::: "memory");
    }

    for (int kt = 0; kt < KT; kt++) {
        if (kt < KT - 1) cp_wait<1>();
        else             cp_wait<0>();
        __syncthreads();

        int lt = kt + NSTG - 1;
        if (lt < KT) {
            float* dstA = smem + (lt % NSTG) * STAGE_FLOATS;
            float* dstB = dstA + BM * BKP;
#pragma unroll
            for (int i = 0; i < 4; i++)
                cp_async16(smem_u32(dstA + sRow[i] * BKP + cOfs[i]),
                           aSrc[i] + lt * BK + cOfs[i]);
#pragma unroll
            for (int i = 0; i < 4; i++)
                cp_async16(smem_u32(dstB + sRow[i] * BKP + cOfs[i]),
                           bSrc[i] + lt * BK + cOfs[i]);
            asm volatile("cp.async.commit_group;" ::: "memory");
        }

        const float* As = smem + (kt % NSTG) * STAGE_FLOATS;
        const float* Bs = As + BM * BKP;
        uint32_t aBase = smem_u32(As + (wm * 64 + aRow) * BKP + aK);
        uint32_t bBase = smem_u32(Bs + (wn * 32 + bRow) * BKP + bK);

#pragma unroll
        for (int k8 = 0; k8 < BK / 8; k8++) {
            uint32_t kOfs = k8 * 8 * 4;
            uint32_t af[4][4], bf2[2][4];
#pragma unroll
            for (int mf = 0; mf < 4; mf++)
                ldsm_x4(af[mf][0], af[mf][1], af[mf][2], af[mf][3],
                        aBase + mf * (16 * BKP * 4) + kOfs);
#pragma unroll
            for (int pr = 0; pr < 2; pr++)
                ldsm_x4(bf2[pr][0], bf2[pr][1], bf2[pr][2], bf2[pr][3],
                        bBase + pr * (16 * BKP * 4) + kOfs);
#pragma unroll
            for (int mf = 0; mf < 4; mf++)
#pragma unroll
                for (int nf = 0; nf < 4; nf++) {
                    uint32_t b0 = bf2[nf >> 1][(nf & 1) * 2];
                    uint32_t b1 = bf2[nf >> 1][(nf & 1) * 2 + 1];
                    asm volatile(
                        "mma.sync.aligned.m16n8k8.row.col.f32.tf32.tf32.f32 "
                        "{%0,%1,%2,%3}, {%4,%5,%6,%7}, {%8,%9}, {%0,%1,%2,%3};"
                        : "+f"(acc[mf][nf][0]), "+f"(acc[mf][nf][1]),
                          "+f"(acc[mf][nf][2]), "+f"(acc[mf][nf][3])
                        : "r"(af[mf][0]), "r"(af[mf][1]),
                          "r"(af[mf][2]), "r"(af[mf][3]),
                          "r"(b0), "r"(b1));
                }
        }
    }

    // fused silu epilogue: nf even = gate, nf odd = up (same cols).
#pragma unroll
    for (int mf = 0; mf < 4; mf++) {
        int r0 = rowBase + wm * 64 + mf * 16 + grp;
#pragma unroll
        for (int pr = 0; pr < 2; pr++) {
            int tcg = 2 * wn + pr;
            int col = colBase + tcg * 8 + tig * 2;
            float* ga = acc[mf][2 * pr];
            float* ua = acc[mf][2 * pr + 1];
            float2 v0 = { silu_mul_rna(ga[0], ua[0]), silu_mul_rna(ga[1], ua[1]) };
            float2 v1 = { silu_mul_rna(ga[2], ua[2]), silu_mul_rna(ga[3], ua[3]) };
            *(float2*)(Hp + (size_t)r0 * N + col) = v0;
            *(float2*)(Hp + (size_t)(r0 + 8) * N + col) = v1;
        }
    }
}

// ----------------- down GEMM body (generic) + merged launcher ---------------
__device__ __forceinline__ void gemm_body(
    const float* __restrict__ Ap, const float* __restrict__ Bp,
    float* __restrict__ Cp, int K, int N, int rowBase, int colBase,
    int mode, const float* __restrict__ rs, float* smem)
{
    int tid = threadIdx.x;
    int w = tid >> 5, lane = tid & 31;
    int wm = w >> 2, wn = w & 3;
    int grp = lane >> 2, tig = lane & 3;
    int q = lane >> 3, r8 = lane & 7;
    int aRow = (q & 1) * 8 + r8, aK = (q >> 1) * 4;
    int bRow = (q >> 1) * 8 + r8, bK = (q & 1) * 4;

    const float* Ag = Ap + (size_t)rowBase * K;
    const float* Bg = Bp + (size_t)colBase * K;

    float acc[4][4][4] = {};
    int KT = K / BK;

#pragma unroll
    for (int pt = 0; pt < NSTG - 1; pt++) {
        float* dstA = smem + pt * STAGE_FLOATS;
        float* dstB = dstA + BM * BKP;
#pragma unroll
        for (int i = 0; i < 4; i++) {
            int idx = tid + i * 256, row = idx >> 3, c = idx & 7;
            cp_async16(smem_u32(dstA + row * BKP + c * 4),
                       Ag + (size_t)row * K + pt * BK + c * 4);
        }
#pragma unroll
        for (int i = 0; i < 4; i++) {
            int idx = tid + i * 256, row = idx >> 3, c = idx & 7;
            cp_async16(smem_u32(dstB + row * BKP + c * 4),
                       Bg + (size_t)row * K + pt * BK + c * 4);
        }
        asm volatile("cp.async.commit_group;" ::: "memory");
    }

    for (int kt = 0; kt < KT; kt++) {
        if (kt < KT - 1) cp_wait<1>();
        else             cp_wait<0>();
        __syncthreads();

        int lt = kt + NSTG - 1;
        if (lt < KT) {
            float* dstA = smem + (lt % NSTG) * STAGE_FLOATS;
            float* dstB = dstA + BM * BKP;
#pragma unroll
            for (int i = 0; i < 4; i++) {
                int idx = tid + i * 256, row = idx >> 3, c = idx & 7;
                cp_async16(smem_u32(dstA + row * BKP + c * 4),
                           Ag + (size_t)row * K + lt * BK + c * 4);
            }
#pragma unroll
            for (int i = 0; i < 4; i++) {
                int idx = tid + i * 256, row = idx >> 3, c = idx & 7;
                cp_async16(smem_u32(dstB + row * BKP + c * 4),
                           Bg + (size_t)row * K + lt * BK + c * 4);
            }
            asm volatile("cp.async.commit_group;" ::: "memory");
        }

        const float* As = smem + (kt % NSTG) * STAGE_FLOATS;
        const float* Bs = As + BM * BKP;
        uint32_t aBase = smem_u32(As + (wm * 64 + aRow) * BKP + aK);
        uint32_t bBase = smem_u32(Bs + (wn * 32 + bRow) * BKP + bK);

#pragma unroll
        for (int k8 = 0; k8 < BK / 8; k8++) {
            uint32_t kOfs = k8 * 8 * 4;
            uint32_t af[4][4], bf2[2][4];
#pragma unroll
            for (int mf = 0; mf < 4; mf++)
                ldsm_x4(af[mf][0], af[mf][1], af[mf][2], af[mf][3],
                        aBase + mf * (16 * BKP * 4) + kOfs);
#pragma unroll
            for (int pr = 0; pr < 2; pr++)
                ldsm_x4(bf2[pr][0], bf2[pr][1], bf2[pr][2], bf2[pr][3],
                        bBase + pr * (16 * BKP * 4) + kOfs);
#pragma unroll
            for (int mf = 0; mf < 4; mf++)
#pragma unroll
                for (int nf = 0; nf < 4; nf++) {
                    uint32_t b0 = bf2[nf >> 1][(nf & 1) * 2];
                    uint32_t b1 = bf2[nf >> 1][(nf & 1) * 2 + 1];
                    asm volatile(
                        "mma.sync.aligned.m16n8k8.row.col.f32.tf32.tf32.f32 "
                        "{%0,%1,%2,%3}, {%4,%5,%6,%7}, {%8,%9}, {%0,%1,%2,%3};"
                        : "+f"(acc[mf][nf][0]), "+f"(acc[mf][nf][1]),
                          "+f"(acc[mf][nf][2]), "+f"(acc[mf][nf][3])
                        : "r"(af[mf][0]), "r"(af[mf][1]),
                          "r"(af[mf][2]), "r"(af[mf][3]),
                          "r"(b0), "r"(b1));
                }
        }
    }

#pragma unroll
    for (int mf = 0; mf < 4; mf++) {
        int r0 = rowBase + wm * 64 + mf * 16 + grp;
        float s0 = mode ? rs[r0] : 1.f;
        float s1 = mode ? rs[r0 + 8] : 1.f;
#pragma unroll
        for (int nf = 0; nf < 4; nf++) {
            int col = colBase + wn * 32 + nf * 8 + tig * 2;
            float2 v0 = { acc[mf][nf][0] * s0, acc[mf][nf][1] * s0 };
            float2 v1 = { acc[mf][nf][2] * s1, acc[mf][nf][3] * s1 };
            *(float2*)(Cp + (size_t)r0 * N + col) = v0;
            *(float2*)(Cp + (size_t)(r0 + 8) * N + col) = v1;
        }
    }
}

// flat grid: [0,256) shared down (K=IFX, rowscale, 8x8 CTA groups),
//            [256,576) dyn down (K=IDY)
__global__ __launch_bounds__(256, 2) void gemm_down_kernel(
    const float* __restrict__ hs, const float* __restrict__ sdw,
    float* __restrict__ outp, const float* __restrict__ wsh,
    const float* __restrict__ h, const float* __restrict__ ddw,
    float* __restrict__ y)
{
    extern __shared__ float smem[];
    int b = blockIdx.x;
    const float *Ap, *Bp; float* Cp; const float* rs; int K, mode, ty, tx;
    if (b < 256) {
        K = IFX; mode = 1; rs = wsh;
        int g = b >> 6, w6 = b & 63;     // 4 groups of 8x8 (32 ty x 8 tx)
        ty = g * 8 + (w6 >> 3);          // 0..31
        tx = w6 & 7;                     // 0..7
        Ap = hs; Bp = sdw; Cp = outp;
    } else {
        K = IDY; mode = 0; rs = nullptr;
        int idx = b - 256;
        int e = idx / 40, t = idx - e * 40;
        ty = t >> 3; tx = t & 7;
        Ap = h + (size_t)e * CAPV * IDY;
        Bp = ddw + (size_t)e * HD * IDY;
        Cp = y + (size_t)e * CAPV * HD;
    }
    gemm_body(Ap, Bp, Cp, K, HD, ty * BM, tx * BN, mode, rs, smem);
}

// ----------------- combine dyn expert outputs into out ----------------------
__global__ __launch_bounds__(256) void combine_kernel(float* __restrict__ out)
{
    int t = blockIdx.x;
    int c = threadIdx.x;
    float4 acc = ((float4*)(out + (size_t)t * HD))[c];
#pragma unroll
    for (int k = 0; k < TOPK; k++) {
        int pos = d_tokpos[t * TOPK + k];
        if (pos >= 0) {
            int e = d_toke[t * TOPK + k];
            float w = d_tokw[t * TOPK + k];
            float4 v = ((const float4*)(d_ybuf + ((size_t)e * CAPV + pos) * HD))[c];
            acc.x += w * v.x; acc.y += w * v.y;
            acc.z += w * v.z; acc.w += w * v.w;
        }
    }
    ((float4*)(out + (size_t)t * HD))[c] = acc;
}

// ----------------- host launcher --------------------------------------------
extern "C" void kernel_launch(void* const* d_in, const int* in_sizes, int n_in,
                              void* d_out, int out_size)
{
    const float* x   = (const float*)d_in[0];
    const float* gw  = (const float*)d_in[1];
    const float* dgw = (const float*)d_in[2];
    const float* duw = (const float*)d_in[3];
    const float* ddw = (const float*)d_in[4];
    const float* sgw = (const float*)d_in[5];
    const float* suw = (const float*)d_in[6];
    const float* sdw = (const float*)d_in[7];
    float* out = (float*)d_out;

    float *p_xe, *p_h, *p_y, *p_hs, *p_wsh, *p_xr;
    float *p_dgw, *p_duw, *p_ddw, *p_sgw, *p_suw, *p_sdw;
    cudaGetSymbolAddress((void**)&p_xe, d_xe);
    cudaGetSymbolAddress((void**)&p_h, d_hbuf);
    cudaGetSymbolAddress((void**)&p_y, d_ybuf);
    cudaGetSymbolAddress((void**)&p_hs, d_hs);
    cudaGetSymbolAddress((void**)&p_wsh, d_wsh);
    cudaGetSymbolAddress((void**)&p_xr, d_xr);
    cudaGetSymbolAddress((void**)&p_dgw, d_dgw_r);
    cudaGetSymbolAddress((void**)&p_duw, d_duw_r);
    cudaGetSymbolAddress((void**)&p_ddw, d_ddw_r);
    cudaGetSymbolAddress((void**)&p_sgw, d_sgw_r);
    cudaGetSymbolAddress((void**)&p_suw, d_suw_r);
    cudaGetSymbolAddress((void**)&p_sdw, d_sdw_r);

    cudaFuncSetAttribute(gemm_gateup_fused,
                         cudaFuncAttributeMaxDynamicSharedMemorySize, GEMM_SMEM);
    cudaFuncSetAttribute(gemm_down_kernel,
                         cudaFuncAttributeMaxDynamicSharedMemorySize, GEMM_SMEM);

    // tf32 rounding prepass (one launch)
    round_all_kernel<<<(int)((ROUND_TOTAL + 255) / 256), 256>>>(
        (const float4*)dgw, (const float4*)duw, (const float4*)ddw,
        (const float4*)sgw, (const float4*)suw, (const float4*)sdw,
        (const float4*)x);

    // routing
    logits_kernel<<<(TT * NE + 7) / 8, 256>>>(x, gw);
    routing_kernel<<<(TT + 255) / 256, 256>>>();
    scan_kernel<<<EDN, 1024>>>();
    finalize_kernel<<<(TT + 255) / 256, 256>>>();
    gather_kernel<<<EDN * CAPV, 256>>>(x);

    // fused gate+up+silu GEMM (shared + dyn), then merged down GEMM
    gemm_gateup_fused<<<1344, 256, GEMM_SMEM>>>(
        p_xr, p_sgw, p_suw, p_hs, p_xe, p_dgw, p_duw, p_h);
    gemm_down_kernel<<<576, 256, GEMM_SMEM>>>(
        p_hs, p_sdw, out, p_wsh, p_h, p_ddw, p_y);

    // add dyn contributions
    combine_kernel<<<TT, 256>>>(out);
}

// round 16
// speedup vs baseline: 1.0114x; 1.0114x over previous
#include <cuda_runtime.h>
#include <math.h>
#include <float.h>
#include <stdint.h>

#define TT   4096
#define HD   1024
#define EDN  8
#define NE   9
#define IDY  512
#define IFX  2048
#define CAPV 640
#define TOPK 4
#define TOPP 0.75f
#define JEPS2 0.2f

// ---- mma.sync tf32 GEMM tiling: CTA 128x128x32, 8 warps (2x4), warp 64x32 --
#define BM   128
#define BN   128
#define BK   32
#define BKP  36
#define NSTG 3
#define STAGE_FLOATS ((BM + BN) * BKP)         // 9216
#define GEMM_SMEM (NSTG * STAGE_FLOATS * 4)    // 110592 B -> 2 CTAs/SM

__device__ __forceinline__ uint32_t smem_u32(const void* p) {
    uint32_t a;
    asm("{ .reg .u64 t; cvta.to.shared.u64 t, %1; cvt.u32.u64 %0, t; }" : "=r"(a) : "l"(p));
    return a;
}
__device__ __forceinline__ void cp_async16(uint32_t dst, const void* src) {
    asm volatile("cp.async.cg.shared.global [%0], [%1], 16;" :: "r"(dst), "l"(src));
}
template<int N> __device__ __forceinline__ void cp_wait() {
    asm volatile("cp.async.wait_group %0;" :: "n"(N) : "memory");
}
__device__ __forceinline__ float rna_tf32(float x) {
    uint32_t u;
    asm("cvt.rna.tf32.f32 %0, %1;" : "=r"(u) : "f"(x));
    return __uint_as_float(u);
}
__device__ __forceinline__ uint32_t rna_tf32_r(uint32_t r) {
    uint32_t u;
    asm("cvt.rna.tf32.f32 %0, %1;" : "=r"(u) : "f"(__uint_as_float(r)));
    return u;
}
__device__ __forceinline__ void ldsm_x4(uint32_t& r0, uint32_t& r1,
                                        uint32_t& r2, uint32_t& r3, uint32_t addr) {
    asm volatile("ldmatrix.sync.aligned.m8n8.x4.shared.b16 {%0,%1,%2,%3}, [%4];"
                 : "=r"(r0), "=r"(r1), "=r"(r2), "=r"(r3) : "r"(addr));
}
__device__ __forceinline__ float silu_mul_rna(float g, float u) {
    return rna_tf32(g / (1.f + expf(-g)) * u);
}

// ----------------- device scratch (static, no allocations) -----------------
__device__ float d_logits[TT * NE];
__device__ int   d_sel[TT * TOPK];
__device__ float d_rw[TT * TOPK];
__device__ unsigned d_maskbits[TT];
__device__ int   d_kept[TT * EDN];
__device__ int   d_counts[EDN];
__device__ int   d_etok[EDN * CAPV];
__device__ int   d_tokpos[TT * TOPK];
__device__ int   d_toke[TT * TOPK];
__device__ float d_tokw[TT * TOPK];
__device__ float d_wsh[TT];
__device__ float d_xe[(size_t)EDN * CAPV * HD];
__device__ float d_hbuf[(size_t)EDN * CAPV * IDY];
__device__ float d_ybuf[(size_t)EDN * CAPV * HD];
__device__ float d_hs[(size_t)TT * IFX];
__device__ float d_xr[(size_t)TT * HD];

// ----------------- K0: round x to tf32 (A operand of shared gate+up) --------
__global__ __launch_bounds__(256) void round_x_kernel(const float4* __restrict__ x)
{
    int i = blockIdx.x * blockDim.x + threadIdx.x;
    if (i >= TT * HD / 4) return;
    float4 v = x[i];
    v.x = rna_tf32(v.x); v.y = rna_tf32(v.y);
    v.z = rna_tf32(v.z); v.w = rna_tf32(v.w);
    ((float4*)d_xr)[i] = v;
}

// ----------------- K1: router logits ---------------------------------------
__global__ __launch_bounds__(256) void logits_kernel(
    const float* __restrict__ x, const float* __restrict__ gw)
{
    int widx = blockIdx.x * 8 + (threadIdx.x >> 5);
    if (widx >= TT * NE) return;
    int t = widx / NE, e = widx - t * NE;
    int lane = threadIdx.x & 31;
    const float4* xr = (const float4*)(x + (size_t)t * HD);
    const float4* wr = (const float4*)(gw + (size_t)e * HD);
    float s = 0.f;
#pragma unroll
    for (int i = 0; i < HD / 128; i++) {
        float4 a = xr[lane + i * 32];
        float4 b = wr[lane + i * 32];
        s += a.x * b.x + a.y * b.y + a.z * b.z + a.w * b.w;
    }
#pragma unroll
    for (int o = 16; o; o >>= 1) s += __shfl_xor_sync(0xffffffffu, s, o);
    if (!lane) d_logits[widx] = s;
}

// ----------------- K2: per-token routing (packs mask bits) ------------------
__global__ void routing_kernel()
{
    int t = blockIdx.x * blockDim.x + threadIdx.x;
    if (t >= TT) return;

    float s[EDN];
#pragma unroll
    for (int e = 0; e < EDN; e++) s[e] = d_logits[t * NE + e];

    float m = s[0];
#pragma unroll
    for (int e = 1; e < EDN; e++) m = fmaxf(m, s[e]);
    float p[EDN]; float den = 0.f;
#pragma unroll
    for (int e = 0; e < EDN; e++) { p[e] = expf(s[e] - m); den += p[e]; }
#pragma unroll
    for (int e = 0; e < EDN; e++) p[e] /= den;
    float sp[EDN];
#pragma unroll
    for (int e = 0; e < EDN; e++) sp[e] = p[e];
    for (int i = 1; i < EDN; i++) {
        float v = sp[i]; int j = i - 1;
        while (j >= 0 && sp[j] < v) { sp[j + 1] = sp[j]; j--; }
        sp[j + 1] = v;
    }
    float c = 0.f; int cnt = 0;
#pragma unroll
    for (int e = 0; e < EDN; e++) { c += sp[e]; if (c < TOPP) cnt++; }
    int dyn_k = min(cnt + 1, TOPK);

    float masked[EDN];
#pragma unroll
    for (int e = 0; e < EDN; e++) masked[e] = s[e];
    float mult[TOPK]; int sel[TOPK];
    for (int k = 0; k < TOPK; k++) {
        float thr = masked[0]; int sl = 0;
        for (int e = 1; e < EDN; e++)
            if (masked[e] > thr) { thr = masked[e]; sl = e; }
        bool keep[EDN];
        float gm = -INFINITY;
        for (int e = 0; e < EDN; e++) {
            float fac = fmaxf(fabsf(s[e]), fabsf(thr));
            float jm = (thr - s[e]) / fac;
            keep[e] = !(jm > JEPS2);
            if (keep[e]) gm = fmaxf(gm, masked[e]);
        }
        float d2 = 0.f;
        for (int e = 0; e < EDN; e++)
            if (keep[e]) d2 += expf(masked[e] - gm);
        mult[k] = expf(thr - gm) / d2;
        sel[k] = sl;
        masked[sl] = -INFINITY;
    }
    float rsum = 0.f;
#pragma unroll
    for (int k = 0; k < TOPK; k++) {
        if (k >= dyn_k) mult[k] = 0.f;
        rsum += mult[k];
    }
    unsigned mk = 0;
#pragma unroll
    for (int k = 0; k < TOPK; k++) {
        float r = mult[k] / rsum;
        d_rw[t * TOPK + k] = r;
        d_sel[t * TOPK + k] = sel[k];
        if (mult[k] > 0.f) mk |= (1u << sel[k]);
    }
    d_maskbits[t] = mk;
}

// ----------------- K3: capacity scan (8 CTAs, 1024 thr, block scan) ---------
__global__ __launch_bounds__(1024) void scan_kernel()
{
    int e = blockIdx.x;
    int lane = threadIdx.x & 31, w = threadIdx.x >> 5;
    __shared__ int woff[32];
    __shared__ int tot_s;
    if (threadIdx.x == 0) d_counts[e] = 0;
    int carry = 0;
    __syncthreads();
    for (int c0 = 0; c0 < TT / 1024; c0++) {
        int t = c0 * 1024 + threadIdx.x;
        int v = (int)((d_maskbits[t] >> e) & 1u);
        unsigned bal = __ballot_sync(0xffffffffu, v);
        int pre = __popc(bal & ((1u << lane) - 1));
        if (lane == 0) woff[w] = __popc(bal);
        __syncthreads();
        if (w == 0) {
            int val = woff[lane];
            int ex = val;
#pragma unroll
            for (int o = 1; o < 32; o <<= 1) {
                int n = __shfl_up_sync(0xffffffffu, ex, o);
                if (lane >= o) ex += n;
            }
            woff[lane] = ex - val;
            if (lane == 31) tot_s = ex;
        }
        __syncthreads();
        int incl = carry + woff[w] + pre + v;
        d_kept[t * EDN + e] = (v && incl <= CAPV) ? 1 : 0;
        carry += tot_s;
        __syncthreads();
    }
}

// ----------------- K4: masked softmax + compaction --------------------------
__global__ void finalize_kernel()
{
    int t = blockIdx.x * blockDim.x + threadIdx.x;
    if (t >= TT) return;
    float l[NE];
#pragma unroll
    for (int i = 0; i < NE; i++) l[i] = d_logits[t * NE + i];
    int km[EDN];
#pragma unroll
    for (int e = 0; e < EDN; e++) km[e] = d_kept[t * EDN + e];

    float m = l[EDN];
#pragma unroll
    for (int e = 0; e < EDN; e++) if (km[e]) m = fmaxf(m, l[e]);
    float den = 0.f, dynsum = 0.f;
#pragma unroll
    for (int e = 0; e < EDN; e++)
        if (km[e]) { float ex = expf(l[e] - m); den += ex; dynsum += ex; }
    float exsh = expf(l[EDN] - m);
    den += exsh;
    d_wsh[t] = exsh / den;
    float sumdyn = dynsum / den;

#pragma unroll
    for (int k = 0; k < TOPK; k++) {
        float r = d_rw[t * TOPK + k];
        int e = d_sel[t * TOPK + k];
        int pos = -1;
        if (r > 0.f && km[e]) {
            pos = atomicAdd(&d_counts[e], 1);
            d_etok[e * CAPV + pos] = t;
            d_toke[t * TOPK + k] = e;
            d_tokw[t * TOPK + k] = r * sumdyn;
        }
        d_tokpos[t * TOPK + k] = pos;
    }
}

// ----------------- K5: gather x rows per expert (tf32-rounded) --------------
__global__ __launch_bounds__(256) void gather_kernel(const float* __restrict__ x)
{
    int b = blockIdx.x;
    int e = b / CAPV, i = b - e * CAPV;
    int c = threadIdx.x;
    float4* dst = (float4*)(d_xe + ((size_t)e * CAPV + i) * HD);
    if (i < d_counts[e]) {
        int t = d_etok[e * CAPV + i];
        float4 v = ((const float4*)(x + (size_t)t * HD))[c];
        v.x = rna_tf32(v.x); v.y = rna_tf32(v.y);
        v.z = rna_tf32(v.z); v.w = rna_tf32(v.w);
        dst[c] = v;
    } else {
        dst[c] = make_float4(0.f, 0.f, 0.f, 0.f);
    }
}

// ===================== fused gate+up GEMM + silu ============================
// CTA computes a 128(M) x 64(cols) h tile: B smem rows interleave gate/up at
// 8-row granularity. Fragment nf even = gate, nf odd = up for SAME cols ->
// thread-local silu. B (weights) read RAW; fragments rounded to tf32 (rna)
// after ldmatrix (bit-identical to pre-rounded memory). K = HD always.
__global__ __launch_bounds__(256, 2) void gemm_gateup_fused(
    const float* __restrict__ xr, const float* __restrict__ sgw,
    const float* __restrict__ suw, float* __restrict__ hsO,
    const float* __restrict__ xe, const float* __restrict__ dgw,
    const float* __restrict__ duw, float* __restrict__ hO)
{
    extern __shared__ float smem[];
    int b = blockIdx.x;
    const float *Ap, *Bg_, *Bu_; float* Hp; int N, ty, tx;
    if (b < 1024) {                      // shared expert: 32 y x 32 x(64-col)
        N = IFX;
        ty = b >> 5; tx = b & 31;
        Ap = xr; Bg_ = sgw; Bu_ = suw; Hp = hsO;
    } else {                             // dyn: 8 experts x (5 y x 8 x)
        N = IDY;
        int idx = b - 1024;              // [0,320)
        int e = idx / 40, t = idx - e * 40;
        ty = t >> 3; tx = t & 7;
        Ap = xe + (size_t)e * CAPV * HD;
        Bg_ = dgw + (size_t)e * IDY * HD;
        Bu_ = duw + (size_t)e * IDY * HD;
        Hp = hO + (size_t)e * CAPV * IDY;
    }
    int rowBase = ty * BM, colBase = tx * 64;
    const int K = HD;

    int tid = threadIdx.x;
    int w = tid >> 5, lane = tid & 31;
    int wm = w >> 2, wn = w & 3;
    int grp = lane >> 2, tig = lane & 3;
    int q = lane >> 3, r8 = lane & 7;
    int aRow = (q & 1) * 8 + r8, aK = (q >> 1) * 4;
    int bRow = (q >> 1) * 8 + r8, bK = (q & 1) * 4;

    const float* aSrc[4];
    const float* bSrc[4];
    int sRow[4];
#pragma unroll
    for (int i = 0; i < 4; i++) {
        int idx = tid + i * 256, row = idx >> 3;
        sRow[i] = row;
        aSrc[i] = Ap + (size_t)(rowBase + row) * K;
        int t8 = row >> 4, sub = (row >> 3) & 1;
        int wRow = colBase + (t8 << 3) + (row & 7);
        bSrc[i] = (sub ? Bu_ : Bg_) + (size_t)wRow * K;
    }
    int cOfs[4];
#pragma unroll
    for (int i = 0; i < 4; i++) cOfs[i] = ((tid + i * 256) & 7) * 4;

    float acc[4][4][4] = {};
    const int KT = K / BK;

#pragma unroll
    for (int pt = 0; pt < NSTG - 1; pt++) {
        float* dstA = smem + pt * STAGE_FLOATS;
        float* dstB = dstA + BM * BKP;
#pragma unroll
        for (int i = 0; i < 4; i++)
            cp_async16(smem_u32(dstA + sRow[i] * BKP + cOfs[i]),
                       aSrc[i] + pt * BK + cOfs[i]);
#pragma unroll
        for (int i = 0; i < 4; i++)
            cp_async16(smem_u32(dstB + sRow[i] * BKP + cOfs[i]),
                       bSrc[i] + pt * BK + cOfs[i]);
        asm volatile("cp.async.commit_group;" ::: "memory");
    }

    for (int kt = 0; kt < KT; kt++) {
        if (kt < KT - 1) cp_wait<1>();
        else             cp_wait<0>();
        __syncthreads();

        int lt = kt + NSTG - 1;
        if (lt < KT) {
            float* dstA = smem + (lt % NSTG) * STAGE_FLOATS;
            float* dstB = dstA + BM * BKP;
#pragma unroll
            for (int i = 0; i < 4; i++)
                cp_async16(smem_u32(dstA + sRow[i] * BKP + cOfs[i]),
                           aSrc[i] + lt * BK + cOfs[i]);
#pragma unroll
            for (int i = 0; i < 4; i++)
                cp_async16(smem_u32(dstB + sRow[i] * BKP + cOfs[i]),
                           bSrc[i] + lt * BK + cOfs[i]);
            asm volatile("cp.async.commit_group;" ::: "memory");
        }

        const float* As = smem + (kt % NSTG) * STAGE_FLOATS;
        const float* Bs = As + BM * BKP;
        uint32_t aBase = smem_u32(As + (wm * 64 + aRow) * BKP + aK);
        uint32_t bBase = smem_u32(Bs + (wn * 32 + bRow) * BKP + bK);

#pragma unroll
        for (int k8 = 0; k8 < BK / 8; k8++) {
            uint32_t kOfs = k8 * 8 * 4;
            uint32_t af[4][4], bf2[2][4];
#pragma unroll
            for (int mf = 0; mf < 4; mf++)
                ldsm_x4(af[mf][0], af[mf][1], af[mf][2], af[mf][3],
                        aBase + mf * (16 * BKP * 4) + kOfs);
#pragma unroll
            for (int pr = 0; pr < 2; pr++) {
                ldsm_x4(bf2[pr][0], bf2[pr][1], bf2[pr][2], bf2[pr][3],
                        bBase + pr * (16 * BKP * 4) + kOfs);
#pragma unroll
                for (int j = 0; j < 4; j++) bf2[pr][j] = rna_tf32_r(bf2[pr][j]);
            }
#pragma unroll
            for (int mf = 0; mf < 4; mf++)
#pragma unroll
                for (int nf = 0; nf < 4; nf++) {
                    uint32_t b0 = bf2[nf >> 1][(nf & 1) * 2];
                    uint32_t b1 = bf2[nf >> 1][(nf & 1) * 2 + 1];
                    asm volatile(
                        "mma.sync.aligned.m16n8k8.row.col.f32.tf32.tf32.f32 "
                        "{%0,%1,%2,%3}, {%4,%5,%6,%7}, {%8,%9}, {%0,%1,%2,%3};"
                        : "+f"(acc[mf][nf][0]), "+f"(acc[mf][nf][1]),
                          "+f"(acc[mf][nf][2]), "+f"(acc[mf][nf][3])
                        : "r"(af[mf][0]), "r"(af[mf][1]),
                          "r"(af[mf][2]), "r"(af[mf][3]),
                          "r"(b0), "r"(b1));
                }
        }
    }

    // fused silu epilogue: nf even = gate, nf odd = up (same cols).
#pragma unroll
    for (int mf = 0; mf < 4; mf++) {
        int r0 = rowBase + wm * 64 + mf * 16 + grp;
#pragma unroll
        for (int pr = 0; pr < 2; pr++) {
            int tcg = 2 * wn + pr;
            int col = colBase + tcg * 8 + tig * 2;
            float* ga = acc[mf][2 * pr];
            float* ua = acc[mf][2 * pr + 1];
            float2 v0 = { silu_mul_rna(ga[0], ua[0]), silu_mul_rna(ga[1], ua[1]) };
            float2 v1 = { silu_mul_rna(ga[2], ua[2]), silu_mul_rna(ga[3], ua[3]) };
            *(float2*)(Hp + (size_t)r0 * N + col) = v0;
            *(float2*)(Hp + (size_t)(r0 + 8) * N + col) = v1;
        }
    }
}

// ----------------- down GEMM body (raw B, register rounding) ----------------
__device__ __forceinline__ void gemm_body(
    const float* __restrict__ Ap, const float* __restrict__ Bp,
    float* __restrict__ Cp, int K, int N, int rowBase, int colBase,
    int mode, const float* __restrict__ rs, float* smem)
{
    int tid = threadIdx.x;
    int w = tid >> 5, lane = tid & 31;
    int wm = w >> 2, wn = w & 3;
    int grp = lane >> 2, tig = lane & 3;
    int q = lane >> 3, r8 = lane & 7;
    int aRow = (q & 1) * 8 + r8, aK = (q >> 1) * 4;
    int bRow = (q >> 1) * 8 + r8, bK = (q & 1) * 4;

    const float* Ag = Ap + (size_t)rowBase * K;
    const float* Bg = Bp + (size_t)colBase * K;

    float acc[4][4][4] = {};
    int KT = K / BK;

#pragma unroll
    for (int pt = 0; pt < NSTG - 1; pt++) {
        float* dstA = smem + pt * STAGE_FLOATS;
        float* dstB = dstA + BM * BKP;
#pragma unroll
        for (int i = 0; i < 4; i++) {
            int idx = tid + i * 256, row = idx >> 3, c = idx & 7;
            cp_async16(smem_u32(dstA + row * BKP + c * 4),
                       Ag + (size_t)row * K + pt * BK + c * 4);
        }
#pragma unroll
        for (int i = 0; i < 4; i++) {
            int idx = tid + i * 256, row = idx >> 3, c = idx & 7;
            cp_async16(smem_u32(dstB + row * BKP + c * 4),
                       Bg + (size_t)row * K + pt * BK + c * 4);
        }
        asm volatile("cp.async.commit_group;" ::: "memory");
    }

    for (int kt = 0; kt < KT; kt++) {
        if (kt < KT - 1) cp_wait<1>();
        else             cp_wait<0>();
        __syncthreads();

        int lt = kt + NSTG - 1;
        if (lt < KT) {
            float* dstA = smem + (lt % NSTG) * STAGE_FLOATS;
            float* dstB = dstA + BM * BKP;
#pragma unroll
            for (int i = 0; i < 4; i++) {
                int idx = tid + i * 256, row = idx >> 3, c = idx & 7;
                cp_async16(smem_u32(dstA + row * BKP + c * 4),
                           Ag + (size_t)row * K + lt * BK + c * 4);
            }
#pragma unroll
            for (int i = 0; i < 4; i++) {
                int idx = tid + i * 256, row = idx >> 3, c = idx & 7;
                cp_async16(smem_u32(dstB + row * BKP + c * 4),
                           Bg + (size_t)row * K + lt * BK + c * 4);
            }
            asm volatile("cp.async.commit_group;" ::: "memory");
        }

        const float* As = smem + (kt % NSTG) * STAGE_FLOATS;
        const float* Bs = As + BM * BKP;
        uint32_t aBase = smem_u32(As + (wm * 64 + aRow) * BKP + aK);
        uint32_t bBase = smem_u32(Bs + (wn * 32 + bRow) * BKP + bK);

#pragma unroll
        for (int k8 = 0; k8 < BK / 8; k8++) {
            uint32_t kOfs = k8 * 8 * 4;
            uint32_t af[4][4], bf2[2][4];
#pragma unroll
            for (int mf = 0; mf < 4; mf++)
                ldsm_x4(af[mf][0], af[mf][1], af[mf][2], af[mf][3],
                        aBase + mf * (16 * BKP * 4) + kOfs);
#pragma unroll
            for (int pr = 0; pr < 2; pr++) {
                ldsm_x4(bf2[pr][0], bf2[pr][1], bf2[pr][2], bf2[pr][3],
                        bBase + pr * (16 * BKP * 4) + kOfs);
#pragma unroll
                for (int j = 0; j < 4; j++) bf2[pr][j] = rna_tf32_r(bf2[pr][j]);
            }
#pragma unroll
            for (int mf = 0; mf < 4; mf++)
#pragma unroll
                for (int nf = 0; nf < 4; nf++) {
                    uint32_t b0 = bf2[nf >> 1][(nf & 1) * 2];
                    uint32_t b1 = bf2[nf >> 1][(nf & 1) * 2 + 1];
                    asm volatile(
                        "mma.sync.aligned.m16n8k8.row.col.f32.tf32.tf32.f32 "
                        "{%0,%1,%2,%3}, {%4,%5,%6,%7}, {%8,%9}, {%0,%1,%2,%3};"
                        : "+f"(acc[mf][nf][0]), "+f"(acc[mf][nf][1]),
                          "+f"(acc[mf][nf][2]), "+f"(acc[mf][nf][3])
                        : "r"(af[mf][0]), "r"(af[mf][1]),
                          "r"(af[mf][2]), "r"(af[mf][3]),
                          "r"(b0), "r"(b1));
                }
        }
    }

#pragma unroll
    for (int mf = 0; mf < 4; mf++) {
        int r0 = rowBase + wm * 64 + mf * 16 + grp;
        float s0 = mode ? rs[r0] : 1.f;
        float s1 = mode ? rs[r0 + 8] : 1.f;
#pragma unroll
        for (int nf = 0; nf < 4; nf++) {
            int col = colBase + wn * 32 + nf * 8 + tig * 2;
            float2 v0 = { acc[mf][nf][0] * s0, acc[mf][nf][1] * s0 };
            float2 v1 = { acc[mf][nf][2] * s1, acc[mf][nf][3] * s1 };
            *(float2*)(Cp + (size_t)r0 * N + col) = v0;
            *(float2*)(Cp + (size_t)(r0 + 8) * N + col) = v1;
        }
    }
}

// flat grid: [0,256) shared down (K=IFX, rowscale), [256,576) dyn down (K=IDY)
__global__ __launch_bounds__(256, 2) void gemm_down_kernel(
    const float* __restrict__ hs, const float* __restrict__ sdw,
    float* __restrict__ outp, const float* __restrict__ wsh,
    const float* __restrict__ h, const float* __restrict__ ddw,
    float* __restrict__ y)
{
    extern __shared__ float smem[];
    int b = blockIdx.x;
    const float *Ap, *Bp; float* Cp; const float* rs; int K, mode, ty, tx;
    if (b < 256) {
        K = IFX; mode = 1; rs = wsh;
        ty = b >> 3; tx = b & 7;
        Ap = hs; Bp = sdw; Cp = outp;
    } else {
        K = IDY; mode = 0; rs = nullptr;
        int idx = b - 256;
        int e = idx / 40, t = idx - e * 40;
        ty = t >> 3; tx = t & 7;
        Ap = h + (size_t)e * CAPV * IDY;
        Bp = ddw + (size_t)e * HD * IDY;
        Cp = y + (size_t)e * CAPV * HD;
    }
    gemm_body(Ap, Bp, Cp, K, HD, ty * BM, tx * BN, mode, rs, smem);
}

// ----------------- combine dyn expert outputs into out ----------------------
__global__ __launch_bounds__(256) void combine_kernel(float* __restrict__ out)
{
    int t = blockIdx.x;
    int c = threadIdx.x;
    float4 acc = ((float4*)(out + (size_t)t * HD))[c];
#pragma unroll
    for (int k = 0; k < TOPK; k++) {
        int pos = d_tokpos[t * TOPK + k];
        if (pos >= 0) {
            int e = d_toke[t * TOPK + k];
            float w = d_tokw[t * TOPK + k];
            float4 v = ((const float4*)(d_ybuf + ((size_t)e * CAPV + pos) * HD))[c];
            acc.x += w * v.x; acc.y += w * v.y;
            acc.z += w * v.z; acc.w += w * v.w;
        }
    }
    ((float4*)(out + (size_t)t * HD))[c] = acc;
}

// ----------------- host launcher --------------------------------------------
extern "C" void kernel_launch(void* const* d_in, const int* in_sizes, int n_in,
                              void* d_out, int out_size)
{
    const float* x   = (const float*)d_in[0];
    const float* gw  = (const float*)d_in[1];
    const float* dgw = (const float*)d_in[2];
    const float* duw = (const float*)d_in[3];
    const float* ddw = (const float*)d_in[4];
    const float* sgw = (const float*)d_in[5];
    const float* suw = (const float*)d_in[6];
    const float* sdw = (const float*)d_in[7];
    float* out = (float*)d_out;

    float *p_xe, *p_h, *p_y, *p_hs, *p_wsh, *p_xr;
    cudaGetSymbolAddress((void**)&p_xe, d_xe);
    cudaGetSymbolAddress((void**)&p_h, d_hbuf);
    cudaGetSymbolAddress((void**)&p_y, d_ybuf);
    cudaGetSymbolAddress((void**)&p_hs, d_hs);
    cudaGetSymbolAddress((void**)&p_wsh, d_wsh);
    cudaGetSymbolAddress((void**)&p_xr, d_xr);

    cudaFuncSetAttribute(gemm_gateup_fused,
                         cudaFuncAttributeMaxDynamicSharedMemorySize, GEMM_SMEM);
    cudaFuncSetAttribute(gemm_down_kernel,
                         cudaFuncAttributeMaxDynamicSharedMemorySize, GEMM_SMEM);

    // x-only tf32 rounding prepass (weights rounded in-register in the GEMMs)
    round_x_kernel<<<(TT * HD / 4 + 255) / 256, 256>>>((const float4*)x);

    // routing
    logits_kernel<<<(TT * NE + 7) / 8, 256>>>(x, gw);
    routing_kernel<<<(TT + 255) / 256, 256>>>();
    scan_kernel<<<EDN, 1024>>>();
    finalize_kernel<<<(TT + 255) / 256, 256>>>();
    gather_kernel<<<EDN * CAPV, 256>>>(x);

    // fused gate+up+silu GEMM (shared + dyn), then merged down GEMM
    gemm_gateup_fused<<<1344, 256, GEMM_SMEM>>>(
        p_xr, sgw, suw, p_hs, p_xe, dgw, duw, p_h);
    gemm_down_kernel<<<576, 256, GEMM_SMEM>>>(
        p_hs, sdw, out, p_wsh, p_h, ddw, p_y);

    // add dyn contributions
    combine_kernel<<<TT, 256>>>(out);
}

// round 17
// speedup vs baseline: 1.0210x; 1.0095x over previous
#include <cuda_runtime.h>
#include <math.h>
#include <float.h>
#include <stdint.h>

#define TT   4096
#define HD   1024
#define EDN  8
#define NE   9
#define IDY  512
#define IFX  2048
#define CAPV 640
#define TOPK 4
#define TOPP 0.75f
#define JEPS2 0.2f

// ---- mma.sync tf32 GEMM tiling: CTA 128x128x32, 8 warps (2x4), warp 64x32 --
#define BM   128
#define BN   128
#define BK   32
#define BKP  36
#define NSTG 3
#define STAGE_FLOATS ((BM + BN) * BKP)         // 9216
#define GEMM_SMEM (NSTG * STAGE_FLOATS * 4)    // 110592 B -> 2 CTAs/SM

__device__ __forceinline__ uint32_t smem_u32(const void* p) {
    uint32_t a;
    asm("{ .reg .u64 t; cvta.to.shared.u64 t, %1; cvt.u32.u64 %0, t; }" : "=r"(a) : "l"(p));
    return a;
}
__device__ __forceinline__ void cp_async16(uint32_t dst, const void* src) {
    asm volatile("cp.async.cg.shared.global [%0], [%1], 16;" :: "r"(dst), "l"(src));
}
template<int N> __device__ __forceinline__ void cp_wait() {
    asm volatile("cp.async.wait_group %0;" :: "n"(N) : "memory");
}
__device__ __forceinline__ float rna_tf32(float x) {
    uint32_t u;
    asm("cvt.rna.tf32.f32 %0, %1;" : "=r"(u) : "f"(x));
    return __uint_as_float(u);
}
__device__ __forceinline__ uint32_t rna_tf32_r(uint32_t r) {
    uint32_t u;
    asm("cvt.rna.tf32.f32 %0, %1;" : "=r"(u) : "f"(__uint_as_float(r)));
    return u;
}
__device__ __forceinline__ void ldsm_x4(uint32_t& r0, uint32_t& r1,
                                        uint32_t& r2, uint32_t& r3, uint32_t addr) {
    asm volatile("ldmatrix.sync.aligned.m8n8.x4.shared.b16 {%0,%1,%2,%3}, [%4];"
                 : "=r"(r0), "=r"(r1), "=r"(r2), "=r"(r3) : "r"(addr));
}
__device__ __forceinline__ float silu_mul_rna(float g, float u) {
    return rna_tf32(g / (1.f + expf(-g)) * u);
}

// ----------------- device scratch (static, no allocations) -----------------
__device__ float d_logits[TT * NE];
__device__ int   d_sel[TT * TOPK];
__device__ float d_rw[TT * TOPK];
__device__ unsigned d_maskbits[TT];
__device__ int   d_kept[TT * EDN];
__device__ int   d_counts[EDN];
__device__ int   d_etok[EDN * CAPV];
__device__ int   d_tokpos[TT * TOPK];
__device__ int   d_toke[TT * TOPK];
__device__ float d_tokw[TT * TOPK];
__device__ float d_wsh[TT];
__device__ float d_xe[(size_t)EDN * CAPV * HD];
__device__ float d_hbuf[(size_t)EDN * CAPV * IDY];
__device__ float d_ybuf[(size_t)EDN * CAPV * HD];
__device__ float d_hs[(size_t)TT * IFX];
__device__ float d_xr[(size_t)TT * HD];

// ----------------- K1: fused router (logits + round-x + routing) ------------
// One warp per token: stream the x row ONCE (also writing the tf32-rounded
// copy), accumulate all 9 expert dots per lane in the same chunk order and
// shfl-xor tree as before (bit-identical logits), lane 0 runs the mixer.
__global__ __launch_bounds__(256) void router_kernel(
    const float* __restrict__ x, const float* __restrict__ gw)
{
    int t = blockIdx.x * 8 + (threadIdx.x >> 5);
    if (t >= TT) return;
    int lane = threadIdx.x & 31;
    const float4* xr4 = (const float4*)(x + (size_t)t * HD);

    float s[NE];
#pragma unroll
    for (int e = 0; e < NE; e++) s[e] = 0.f;
#pragma unroll
    for (int i = 0; i < HD / 128; i++) {
        float4 a = xr4[lane + i * 32];
        float4 ar;
        ar.x = rna_tf32(a.x); ar.y = rna_tf32(a.y);
        ar.z = rna_tf32(a.z); ar.w = rna_tf32(a.w);
        ((float4*)d_xr)[(size_t)t * (HD / 4) + i * 32 + lane] = ar;
#pragma unroll
        for (int e = 0; e < NE; e++) {
            float4 b = ((const float4*)(gw + (size_t)e * HD))[lane + i * 32];
            s[e] += a.x * b.x + a.y * b.y + a.z * b.z + a.w * b.w;
        }
    }
#pragma unroll
    for (int e = 0; e < NE; e++)
#pragma unroll
        for (int o = 16; o; o >>= 1)
            s[e] += __shfl_xor_sync(0xffffffffu, s[e], o);

    if (lane) return;
#pragma unroll
    for (int e = 0; e < NE; e++) d_logits[t * NE + e] = s[e];

    // ---- routing (identical logic to previous routing_kernel) ----
    float m = s[0];
#pragma unroll
    for (int e = 1; e < EDN; e++) m = fmaxf(m, s[e]);
    float p[EDN]; float den = 0.f;
#pragma unroll
    for (int e = 0; e < EDN; e++) { p[e] = expf(s[e] - m); den += p[e]; }
#pragma unroll
    for (int e = 0; e < EDN; e++) p[e] /= den;
    float sp[EDN];
#pragma unroll
    for (int e = 0; e < EDN; e++) sp[e] = p[e];
    for (int i = 1; i < EDN; i++) {
        float v = sp[i]; int j = i - 1;
        while (j >= 0 && sp[j] < v) { sp[j + 1] = sp[j]; j--; }
        sp[j + 1] = v;
    }
    float c = 0.f; int cnt = 0;
#pragma unroll
    for (int e = 0; e < EDN; e++) { c += sp[e]; if (c < TOPP) cnt++; }
    int dyn_k = min(cnt + 1, TOPK);

    float masked[EDN];
#pragma unroll
    for (int e = 0; e < EDN; e++) masked[e] = s[e];
    float mult[TOPK]; int sel[TOPK];
    for (int k = 0; k < TOPK; k++) {
        float thr = masked[0]; int sl = 0;
        for (int e = 1; e < EDN; e++)
            if (masked[e] > thr) { thr = masked[e]; sl = e; }
        bool keep[EDN];
        float gm = -INFINITY;
        for (int e = 0; e < EDN; e++) {
            float fac = fmaxf(fabsf(s[e]), fabsf(thr));
            float jm = (thr - s[e]) / fac;
            keep[e] = !(jm > JEPS2);
            if (keep[e]) gm = fmaxf(gm, masked[e]);
        }
        float d2 = 0.f;
        for (int e = 0; e < EDN; e++)
            if (keep[e]) d2 += expf(masked[e] - gm);
        mult[k] = expf(thr - gm) / d2;
        sel[k] = sl;
        masked[sl] = -INFINITY;
    }
    float rsum = 0.f;
#pragma unroll
    for (int k = 0; k < TOPK; k++) {
        if (k >= dyn_k) mult[k] = 0.f;
        rsum += mult[k];
    }
    unsigned mk = 0;
#pragma unroll
    for (int k = 0; k < TOPK; k++) {
        float r = mult[k] / rsum;
        d_rw[t * TOPK + k] = r;
        d_sel[t * TOPK + k] = sel[k];
        if (mult[k] > 0.f) mk |= (1u << sel[k]);
    }
    d_maskbits[t] = mk;
}

// ----------------- K3: capacity scan (8 CTAs, 1024 thr, block scan) ---------
__global__ __launch_bounds__(1024) void scan_kernel()
{
    int e = blockIdx.x;
    int lane = threadIdx.x & 31, w = threadIdx.x >> 5;
    __shared__ int woff[32];
    __shared__ int tot_s;
    if (threadIdx.x == 0) d_counts[e] = 0;
    int carry = 0;
    __syncthreads();
    for (int c0 = 0; c0 < TT / 1024; c0++) {
        int t = c0 * 1024 + threadIdx.x;
        int v = (int)((d_maskbits[t] >> e) & 1u);
        unsigned bal = __ballot_sync(0xffffffffu, v);
        int pre = __popc(bal & ((1u << lane) - 1));
        if (lane == 0) woff[w] = __popc(bal);
        __syncthreads();
        if (w == 0) {
            int val = woff[lane];
            int ex = val;
#pragma unroll
            for (int o = 1; o < 32; o <<= 1) {
                int n = __shfl_up_sync(0xffffffffu, ex, o);
                if (lane >= o) ex += n;
            }
            woff[lane] = ex - val;
            if (lane == 31) tot_s = ex;
        }
        __syncthreads();
        int incl = carry + woff[w] + pre + v;
        d_kept[t * EDN + e] = (v && incl <= CAPV) ? 1 : 0;
        carry += tot_s;
        __syncthreads();
    }
}

// ----------------- K4: masked softmax + compaction --------------------------
__global__ void finalize_kernel()
{
    int t = blockIdx.x * blockDim.x + threadIdx.x;
    if (t >= TT) return;
    float l[NE];
#pragma unroll
    for (int i = 0; i < NE; i++) l[i] = d_logits[t * NE + i];
    int km[EDN];
#pragma unroll
    for (int e = 0; e < EDN; e++) km[e] = d_kept[t * EDN + e];

    float m = l[EDN];
#pragma unroll
    for (int e = 0; e < EDN; e++) if (km[e]) m = fmaxf(m, l[e]);
    float den = 0.f, dynsum = 0.f;
#pragma unroll
    for (int e = 0; e < EDN; e++)
        if (km[e]) { float ex = expf(l[e] - m); den += ex; dynsum += ex; }
    float exsh = expf(l[EDN] - m);
    den += exsh;
    d_wsh[t] = exsh / den;
    float sumdyn = dynsum / den;

#pragma unroll
    for (int k = 0; k < TOPK; k++) {
        float r = d_rw[t * TOPK + k];
        int e = d_sel[t * TOPK + k];
        int pos = -1;
        if (r > 0.f && km[e]) {
            pos = atomicAdd(&d_counts[e], 1);
            d_etok[e * CAPV + pos] = t;
            d_toke[t * TOPK + k] = e;
            d_tokw[t * TOPK + k] = r * sumdyn;
        }
        d_tokpos[t * TOPK + k] = pos;
    }
}

// ----------------- K5: gather x rows per expert (tf32-rounded) --------------
__global__ __launch_bounds__(256) void gather_kernel(const float* __restrict__ x)
{
    int b = blockIdx.x;
    int e = b / CAPV, i = b - e * CAPV;
    int c = threadIdx.x;
    float4* dst = (float4*)(d_xe + ((size_t)e * CAPV + i) * HD);
    if (i < d_counts[e]) {
        int t = d_etok[e * CAPV + i];
        float4 v = ((const float4*)(x + (size_t)t * HD))[c];
        v.x = rna_tf32(v.x); v.y = rna_tf32(v.y);
        v.z = rna_tf32(v.z); v.w = rna_tf32(v.w);
        dst[c] = v;
    } else {
        dst[c] = make_float4(0.f, 0.f, 0.f, 0.f);
    }
}

// ===================== fused gate+up GEMM + silu ============================
// CTA computes a 128(M) x 64(cols) h tile: B smem rows interleave gate/up at
// 8-row granularity. Fragment nf even = gate, nf odd = up for SAME cols ->
// thread-local silu. B (weights) read RAW; fragments rounded to tf32 (rna)
// after ldmatrix (bit-identical to pre-rounded memory). K = HD always.
__global__ __launch_bounds__(256, 2) void gemm_gateup_fused(
    const float* __restrict__ xr, const float* __restrict__ sgw,
    const float* __restrict__ suw, float* __restrict__ hsO,
    const float* __restrict__ xe, const float* __restrict__ dgw,
    const float* __restrict__ duw, float* __restrict__ hO)
{
    extern __shared__ float smem[];
    int b = blockIdx.x;
    const float *Ap, *Bg_, *Bu_; float* Hp; int N, ty, tx;
    if (b < 1024) {                      // shared expert: 32 y x 32 x(64-col)
        N = IFX;
        ty = b >> 5; tx = b & 31;
        Ap = xr; Bg_ = sgw; Bu_ = suw; Hp = hsO;
    } else {                             // dyn: 8 experts x (5 y x 8 x)
        N = IDY;
        int idx = b - 1024;              // [0,320)
        int e = idx / 40, t = idx - e * 40;
        ty = t >> 3; tx = t & 7;
        Ap = xe + (size_t)e * CAPV * HD;
        Bg_ = dgw + (size_t)e * IDY * HD;
        Bu_ = duw + (size_t)e * IDY * HD;
        Hp = hO + (size_t)e * CAPV * IDY;
    }
    int rowBase = ty * BM, colBase = tx * 64;
    const int K = HD;

    int tid = threadIdx.x;
    int w = tid >> 5, lane = tid & 31;
    int wm = w >> 2, wn = w & 3;
    int grp = lane >> 2, tig = lane & 3;
    int q = lane >> 3, r8 = lane & 7;
    int aRow = (q & 1) * 8 + r8, aK = (q >> 1) * 4;
    int bRow = (q >> 1) * 8 + r8, bK = (q & 1) * 4;

    const float* aSrc[4];
    const float* bSrc[4];
    int sRow[4];
#pragma unroll
    for (int i = 0; i < 4; i++) {
        int idx = tid + i * 256, row = idx >> 3;
        sRow[i] = row;
        aSrc[i] = Ap + (size_t)(rowBase + row) * K;
        int t8 = row >> 4, sub = (row >> 3) & 1;
        int wRow = colBase + (t8 << 3) + (row & 7);
        bSrc[i] = (sub ? Bu_ : Bg_) + (size_t)wRow * K;
    }
    int cOfs[4];
#pragma unroll
    for (int i = 0; i < 4; i++) cOfs[i] = ((tid + i * 256) & 7) * 4;

    float acc[4][4][4] = {};
    const int KT = K / BK;

#pragma unroll
    for (int pt = 0; pt < NSTG - 1; pt++) {
        float* dstA = smem + pt * STAGE_FLOATS;
        float* dstB = dstA + BM * BKP;
#pragma unroll
        for (int i = 0; i < 4; i++)
            cp_async16(smem_u32(dstA + sRow[i] * BKP + cOfs[i]),
                       aSrc[i] + pt * BK + cOfs[i]);
#pragma unroll
        for (int i = 0; i < 4; i++)
            cp_async16(smem_u32(dstB + sRow[i] * BKP + cOfs[i]),
                       bSrc[i] + pt * BK + cOfs[i]);
        asm volatile("cp.async.commit_group;" ::: "memory");
    }

    for (int kt = 0; kt < KT; kt++) {
        if (kt < KT - 1) cp_wait<1>();
        else             cp_wait<0>();
        __syncthreads();

        int lt = kt + NSTG - 1;
        if (lt < KT) {
            float* dstA = smem + (lt % NSTG) * STAGE_FLOATS;
            float* dstB = dstA + BM * BKP;
#pragma unroll
            for (int i = 0; i < 4; i++)
                cp_async16(smem_u32(dstA + sRow[i] * BKP + cOfs[i]),
                           aSrc[i] + lt * BK + cOfs[i]);
#pragma unroll
            for (int i = 0; i < 4; i++)
                cp_async16(smem_u32(dstB + sRow[i] * BKP + cOfs[i]),
                           bSrc[i] + lt * BK + cOfs[i]);
            asm volatile("cp.async.commit_group;" ::: "memory");
        }

        const float* As = smem + (kt % NSTG) * STAGE_FLOATS;
        const float* Bs = As + BM * BKP;
        uint32_t aBase = smem_u32(As + (wm * 64 + aRow) * BKP + aK);
        uint32_t bBase = smem_u32(Bs + (wn * 32 + bRow) * BKP + bK);

#pragma unroll
        for (int k8 = 0; k8 < BK / 8; k8++) {
            uint32_t kOfs = k8 * 8 * 4;
            uint32_t af[4][4], bf2[2][4];
#pragma unroll
            for (int mf = 0; mf < 4; mf++)
                ldsm_x4(af[mf][0], af[mf][1], af[mf][2], af[mf][3],
                        aBase + mf * (16 * BKP * 4) + kOfs);
#pragma unroll
            for (int pr = 0; pr < 2; pr++) {
                ldsm_x4(bf2[pr][0], bf2[pr][1], bf2[pr][2], bf2[pr][3],
                        bBase + pr * (16 * BKP * 4) + kOfs);
#pragma unroll
                for (int j = 0; j < 4; j++) bf2[pr][j] = rna_tf32_r(bf2[pr][j]);
            }
#pragma unroll
            for (int mf = 0; mf < 4; mf++)
#pragma unroll
                for (int nf = 0; nf < 4; nf++) {
                    uint32_t b0 = bf2[nf >> 1][(nf & 1) * 2];
                    uint32_t b1 = bf2[nf >> 1][(nf & 1) * 2 + 1];
                    asm volatile(
                        "mma.sync.aligned.m16n8k8.row.col.f32.tf32.tf32.f32 "
                        "{%0,%1,%2,%3}, {%4,%5,%6,%7}, {%8,%9}, {%0,%1,%2,%3};"
                        : "+f"(acc[mf][nf][0]), "+f"(acc[mf][nf][1]),
                          "+f"(acc[mf][nf][2]), "+f"(acc[mf][nf][3])
                        : "r"(af[mf][0]), "r"(af[mf][1]),
                          "r"(af[mf][2]), "r"(af[mf][3]),
                          "r"(b0), "r"(b1));
                }
        }
    }

    // fused silu epilogue: nf even = gate, nf odd = up (same cols).
#pragma unroll
    for (int mf = 0; mf < 4; mf++) {
        int r0 = rowBase + wm * 64 + mf * 16 + grp;
#pragma unroll
        for (int pr = 0; pr < 2; pr++) {
            int tcg = 2 * wn + pr;
            int col = colBase + tcg * 8 + tig * 2;
            float* ga = acc[mf][2 * pr];
            float* ua = acc[mf][2 * pr + 1];
            float2 v0 = { silu_mul_rna(ga[0], ua[0]), silu_mul_rna(ga[1], ua[1]) };
            float2 v1 = { silu_mul_rna(ga[2], ua[2]), silu_mul_rna(ga[3], ua[3]) };
            *(float2*)(Hp + (size_t)r0 * N + col) = v0;
            *(float2*)(Hp + (size_t)(r0 + 8) * N + col) = v1;
        }
    }
}

// ----------------- down GEMM body (raw B, register rounding) ----------------
__device__ __forceinline__ void gemm_body(
    const float* __restrict__ Ap, const float* __restrict__ Bp,
    float* __restrict__ Cp, int K, int N, int rowBase, int colBase,
    int mode, const float* __restrict__ rs, float* smem)
{
    int tid = threadIdx.x;
    int w = tid >> 5, lane = tid & 31;
    int wm = w >> 2, wn = w & 3;
    int grp = lane >> 2, tig = lane & 3;
    int q = lane >> 3, r8 = lane & 7;
    int aRow = (q & 1) * 8 + r8, aK = (q >> 1) * 4;
    int bRow = (q >> 1) * 8 + r8, bK = (q & 1) * 4;

    const float* Ag = Ap + (size_t)rowBase * K;
    const float* Bg = Bp + (size_t)colBase * K;

    float acc[4][4][4] = {};
    int KT = K / BK;

#pragma unroll
    for (int pt = 0; pt < NSTG - 1; pt++) {
        float* dstA = smem + pt * STAGE_FLOATS;
        float* dstB = dstA + BM * BKP;
#pragma unroll
        for (int i = 0; i < 4; i++) {
            int idx = tid + i * 256, row = idx >> 3, c = idx & 7;
            cp_async16(smem_u32(dstA + row * BKP + c * 4),
                       Ag + (size_t)row * K + pt * BK + c * 4);
        }
#pragma unroll
        for (int i = 0; i < 4; i++) {
            int idx = tid + i * 256, row = idx >> 3, c = idx & 7;
            cp_async16(smem_u32(dstB + row * BKP + c * 4),
                       Bg + (size_t)row * K + pt * BK + c * 4);
        }
        asm volatile("cp.async.commit_group;" ::: "memory");
    }

    for (int kt = 0; kt < KT; kt++) {
        if (kt < KT - 1) cp_wait<1>();
        else             cp_wait<0>();
        __syncthreads();

        int lt = kt + NSTG - 1;
        if (lt < KT) {
            float* dstA = smem + (lt % NSTG) * STAGE_FLOATS;
            float* dstB = dstA + BM * BKP;
#pragma unroll
            for (int i = 0; i < 4; i++) {
                int idx = tid + i * 256, row = idx >> 3, c = idx & 7;
                cp_async16(smem_u32(dstA + row * BKP + c * 4),
                           Ag + (size_t)row * K + lt * BK + c * 4);
            }
#pragma unroll
            for (int i = 0; i < 4; i++) {
                int idx = tid + i * 256, row = idx >> 3, c = idx & 7;
                cp_async16(smem_u32(dstB + row * BKP + c * 4),
                           Bg + (size_t)row * K + lt * BK + c * 4);
            }
            asm volatile("cp.async.commit_group;" ::: "memory");
        }

        const float* As = smem + (kt % NSTG) * STAGE_FLOATS;
        const float* Bs = As + BM * BKP;
        uint32_t aBase = smem_u32(As + (wm * 64 + aRow) * BKP + aK);
        uint32_t bBase = smem_u32(Bs + (wn * 32 + bRow) * BKP + bK);

#pragma unroll
        for (int k8 = 0; k8 < BK / 8; k8++) {
            uint32_t kOfs = k8 * 8 * 4;
            uint32_t af[4][4], bf2[2][4];
#pragma unroll
            for (int mf = 0; mf < 4; mf++)
                ldsm_x4(af[mf][0], af[mf][1], af[mf][2], af[mf][3],
                        aBase + mf * (16 * BKP * 4) + kOfs);
#pragma unroll
            for (int pr = 0; pr < 2; pr++) {
                ldsm_x4(bf2[pr][0], bf2[pr][1], bf2[pr][2], bf2[pr][3],
                        bBase + pr * (16 * BKP * 4) + kOfs);
#pragma unroll
                for (int j = 0; j < 4; j++) bf2[pr][j] = rna_tf32_r(bf2[pr][j]);
            }
#pragma unroll
            for (int mf = 0; mf < 4; mf++)
#pragma unroll
                for (int nf = 0; nf < 4; nf++) {
                    uint32_t b0 = bf2[nf >> 1][(nf & 1) * 2];
                    uint32_t b1 = bf2[nf >> 1][(nf & 1) * 2 + 1];
                    asm volatile(
                        "mma.sync.aligned.m16n8k8.row.col.f32.tf32.tf32.f32 "
                        "{%0,%1,%2,%3}, {%4,%5,%6,%7}, {%8,%9}, {%0,%1,%2,%3};"
                        : "+f"(acc[mf][nf][0]), "+f"(acc[mf][nf][1]),
                          "+f"(acc[mf][nf][2]), "+f"(acc[mf][nf][3])
                        : "r"(af[mf][0]), "r"(af[mf][1]),
                          "r"(af[mf][2]), "r"(af[mf][3]),
                          "r"(b0), "r"(b1));
                }
        }
    }

#pragma unroll
    for (int mf = 0; mf < 4; mf++) {
        int r0 = rowBase + wm * 64 + mf * 16 + grp;
        float s0 = mode ? rs[r0] : 1.f;
        float s1 = mode ? rs[r0 + 8] : 1.f;
#pragma unroll
        for (int nf = 0; nf < 4; nf++) {
            int col = colBase + wn * 32 + nf * 8 + tig * 2;
            float2 v0 = { acc[mf][nf][0] * s0, acc[mf][nf][1] * s0 };
            float2 v1 = { acc[mf][nf][2] * s1, acc[mf][nf][3] * s1 };
            *(float2*)(Cp + (size_t)r0 * N + col) = v0;
            *(float2*)(Cp + (size_t)(r0 + 8) * N + col) = v1;
        }
    }
}

// flat grid: [0,256) shared down (K=IFX, rowscale), [256,576) dyn down (K=IDY)
__global__ __launch_bounds__(256, 2) void gemm_down_kernel(
    const float* __restrict__ hs, const float* __restrict__ sdw,
    float* __restrict__ outp, const float* __restrict__ wsh,
    const float* __restrict__ h, const float* __restrict__ ddw,
    float* __restrict__ y)
{
    extern __shared__ float smem[];
    int b = blockIdx.x;
    const float *Ap, *Bp; float* Cp; const float* rs; int K, mode, ty, tx;
    if (b < 256) {
        K = IFX; mode = 1; rs = wsh;
        ty = b >> 3; tx = b & 7;
        Ap = hs; Bp = sdw; Cp = outp;
    } else {
        K = IDY; mode = 0; rs = nullptr;
        int idx = b - 256;
        int e = idx / 40, t = idx - e * 40;
        ty = t >> 3; tx = t & 7;
        Ap = h + (size_t)e * CAPV * IDY;
        Bp = ddw + (size_t)e * HD * IDY;
        Cp = y + (size_t)e * CAPV * HD;
    }
    gemm_body(Ap, Bp, Cp, K, HD, ty * BM, tx * BN, mode, rs, smem);
}

// ----------------- combine dyn expert outputs into out ----------------------
__global__ __launch_bounds__(256) void combine_kernel(float* __restrict__ out)
{
    int t = blockIdx.x;
    int c = threadIdx.x;
    float4 acc = ((float4*)(out + (size_t)t * HD))[c];
#pragma unroll
    for (int k = 0; k < TOPK; k++) {
        int pos = d_tokpos[t * TOPK + k];
        if (pos >= 0) {
            int e = d_toke[t * TOPK + k];
            float w = d_tokw[t * TOPK + k];
            float4 v = ((const float4*)(d_ybuf + ((size_t)e * CAPV + pos) * HD))[c];
            acc.x += w * v.x; acc.y += w * v.y;
            acc.z += w * v.z; acc.w += w * v.w;
        }
    }
    ((float4*)(out + (size_t)t * HD))[c] = acc;
}

// ----------------- host launcher --------------------------------------------
extern "C" void kernel_launch(void* const* d_in, const int* in_sizes, int n_in,
                              void* d_out, int out_size)
{
    const float* x   = (const float*)d_in[0];
    const float* gw  = (const float*)d_in[1];
    const float* dgw = (const float*)d_in[2];
    const float* duw = (const float*)d_in[3];
    const float* ddw = (const float*)d_in[4];
    const float* sgw = (const float*)d_in[5];
    const float* suw = (const float*)d_in[6];
    const float* sdw = (const float*)d_in[7];
    float* out = (float*)d_out;

    float *p_xe, *p_h, *p_y, *p_hs, *p_wsh, *p_xr;
    cudaGetSymbolAddress((void**)&p_xe, d_xe);
    cudaGetSymbolAddress((void**)&p_h, d_hbuf);
    cudaGetSymbolAddress((void**)&p_y, d_ybuf);
    cudaGetSymbolAddress((void**)&p_hs, d_hs);
    cudaGetSymbolAddress((void**)&p_wsh, d_wsh);
    cudaGetSymbolAddress((void**)&p_xr, d_xr);

    cudaFuncSetAttribute(gemm_gateup_fused,
                         cudaFuncAttributeMaxDynamicSharedMemorySize, GEMM_SMEM);
    cudaFuncSetAttribute(gemm_down_kernel,
                         cudaFuncAttributeMaxDynamicSharedMemorySize, GEMM_SMEM);

    // fused router: logits + tf32-rounded x + routing, one launch
    router_kernel<<<(TT + 7) / 8, 256>>>(x, gw);
    scan_kernel<<<EDN, 1024>>>();
    finalize_kernel<<<(TT + 255) / 256, 256>>>();
    gather_kernel<<<EDN * CAPV, 256>>>(x);

    // fused gate+up+silu GEMM (shared + dyn), then merged down GEMM
    gemm_gateup_fused<<<1344, 256, GEMM_SMEM>>>(
        p_xr, sgw, suw, p_hs, p_xe, dgw, duw, p_h);
    gemm_down_kernel<<<576, 256, GEMM_SMEM>>>(
        p_hs, sdw, out, p_wsh, p_h, ddw, p_y);

    // add dyn contributions
    combine_kernel<<<TT, 256>>>(out);
}